// round 4
// baseline (speedup 1.0000x reference)
#include <cuda_runtime.h>

// Problem constants (z: (4,64,16,32,32) f32, emb: (1024,64) f32)
#define NBATCH 4
#define NC     64
#define SP     16384            // 16*32*32 spatial per batch
#define NROWS  (NBATCH * SP)    // 65536
#define KCODES 1024
#define TK     64               // codebook tile per smem pass
#define NTILES (KCODES / TK)    // 16
#define NZQ    (NBATCH * NC * SP)  // 4194304
#define BLK    128
#define NBLOCKS (NROWS / BLK)   // 512

__device__ double g_partial[NBLOCKS];
__device__ unsigned g_ctr = 0;

// ---------------------------------------------------------------------------
// cp.async helpers
// ---------------------------------------------------------------------------
__device__ __forceinline__ void cp_async16(unsigned smem_addr, const void* gptr) {
    asm volatile("cp.async.cg.shared.global [%0], [%1], 16;\n"
                 :: "r"(smem_addr), "l"(gptr));
}
__device__ __forceinline__ void cp_commit() {
    asm volatile("cp.async.commit_group;\n");
}
template <int N>
__device__ __forceinline__ void cp_wait() {
    asm volatile("cp.async.wait_group %0;\n" :: "n"(N));
}

// ---------------------------------------------------------------------------
// Single fused kernel: e2 prep (per block), VQ argmin sweep, STE epilogue,
// and last-block deterministic loss finalization.
// ---------------------------------------------------------------------------
__global__ void __launch_bounds__(BLK)
vq_fused_kernel(const float* __restrict__ z, const float* __restrict__ emb,
                float* __restrict__ out, int write_idx, int write_loss) {
    __shared__ __align__(16) float se[2][TK * NC];   // 2 x 16 KB codebook tiles
    __shared__ __align__(16) float e2s[KCODES];      // 4 KB: all code norms
    __shared__ float wsum[BLK / 32];
    __shared__ double dsum[BLK];
    __shared__ int is_last;

    const int tid = threadIdx.x;
    const int row = blockIdx.x * BLK + tid;
    const int b = row >> 14;           // row / SP
    const int s = row & (SP - 1);      // row % SP

    const float* zp = z + (size_t)b * NC * SP + s;

    // Issue tile 0 and tile 1 codebook loads up front (depth-2 cp.async).
    {
#pragma unroll
        for (int t = 0; t < 2; t++) {
            unsigned sb = (unsigned)__cvta_generic_to_shared(&se[t][0]);
            const char* gb = (const char*)(emb + (size_t)t * TK * NC);
#pragma unroll
            for (int j = 0; j < (TK * NC * 4) / (BLK * 16); j++)
                cp_async16(sb + (tid + j * BLK) * 16, gb + (tid + j * BLK) * 16);
            cp_commit();
        }
    }

    // Per-block e2 (identical expression to the old prep_kernel → identical
    // rounding). emb is 256 KB and L2-resident after the first blocks touch it.
    for (int k = tid; k < KCODES; k += BLK) {
        const float4* e = (const float4*)(emb + (size_t)k * NC);
        float sacc = 0.f;
#pragma unroll
        for (int i = 0; i < NC / 4; i++) {
            float4 v = e[i];
            sacc += v.x * v.x + v.y * v.y + v.z * v.z + v.w * v.w;
        }
        e2s[k] = sacc;
    }

    // Load this row's 64 z values (coalesced: stride SP per channel)
    float zv[NC];
#pragma unroll
    for (int c = 0; c < NC; c++) zv[c] = zp[(size_t)c * SP];

    // z2 via balanced pairwise tree (IDENTICAL to round 1)
    float t32[32];
#pragma unroll
    for (int i = 0; i < 32; i++)
        t32[i] = __fadd_rn(__fmul_rn(zv[2 * i], zv[2 * i]),
                           __fmul_rn(zv[2 * i + 1], zv[2 * i + 1]));
#pragma unroll
    for (int st = 16; st >= 1; st >>= 1)
#pragma unroll
        for (int i = 0; i < 16; i++)
            if (i < st) t32[i] = __fadd_rn(t32[i], t32[i + st]);
    const float z2 = t32[0];

    // Pack z into 32 f32x2 registers: zr[j] = (z[2j], z[2j+1])
    unsigned long long zr[NC / 2];
#pragma unroll
    for (int j = 0; j < NC / 2; j++)
        asm("mov.b64 %0, {%1, %2};" : "=l"(zr[j]) : "f"(zv[2 * j]), "f"(zv[2 * j + 1]));

    __syncthreads();   // e2s ready for all threads

    float best = __int_as_float(0x7f800000);
    int bk = 0;

    for (int t = 0; t < NTILES; t++) {
        if (t < NTILES - 1) cp_wait<1>(); else cp_wait<0>();
        __syncthreads();

        const int buf = t & 1;
        const int k0 = t * TK;

#pragma unroll 4
        for (int kk = 0; kk < TK; kk++) {
            const ulonglong2* ep = (const ulonglong2*)(&se[buf][kk * NC]);
            unsigned long long a0 = 0ull, a1 = 0ull, a2 = 0ull, a3 = 0ull;
#pragma unroll
            for (int i = 0; i < 8; i++) {
                ulonglong2 e01 = ep[2 * i];
                ulonglong2 e23 = ep[2 * i + 1];
                asm("fma.rn.f32x2 %0, %1, %2, %0;" : "+l"(a0) : "l"(zr[4 * i + 0]), "l"(e01.x));
                asm("fma.rn.f32x2 %0, %1, %2, %0;" : "+l"(a1) : "l"(zr[4 * i + 1]), "l"(e01.y));
                asm("fma.rn.f32x2 %0, %1, %2, %0;" : "+l"(a2) : "l"(zr[4 * i + 2]), "l"(e23.x));
                asm("fma.rn.f32x2 %0, %1, %2, %0;" : "+l"(a3) : "l"(zr[4 * i + 3]), "l"(e23.y));
            }
            asm("add.rn.f32x2 %0, %0, %1;" : "+l"(a0) : "l"(a1));
            asm("add.rn.f32x2 %0, %0, %1;" : "+l"(a2) : "l"(a3));
            asm("add.rn.f32x2 %0, %0, %1;" : "+l"(a0) : "l"(a2));
            float lo, hi;
            asm("mov.b64 {%0, %1}, %2;" : "=f"(lo), "=f"(hi) : "l"(a0));
            const float dot = __fadd_rn(lo, hi);
            // Reference rounding: d = fl(fl(z2 + e2_k) - 2*dot)
            const float score = __fsub_rn(__fadd_rn(z2, e2s[k0 + kk]), 2.0f * dot);
            if (score < best) { best = score; bk = k0 + kk; }
        }

        __syncthreads();
        // Refill the buffer just consumed with tile t+2
        if (t + 2 < NTILES) {
            unsigned sb = (unsigned)__cvta_generic_to_shared(&se[buf][0]);
            const char* gb = (const char*)(emb + (size_t)(t + 2) * TK * NC);
#pragma unroll
            for (int j = 0; j < (TK * NC * 4) / (BLK * 16); j++)
                cp_async16(sb + (tid + j * BLK) * 16, gb + (tid + j * BLK) * 16);
            cp_commit();
        }
    }

    // Epilogue (IDENTICAL numerics to round 1): gather winning code, STE
    // output, loss partial, index.
    const float4* eb4 = (const float4*)(emb + (size_t)bk * NC);
    float* oz = out + (size_t)b * NC * SP + s;
    float lsum = 0.f;
#pragma unroll
    for (int i = 0; i < NC / 4; i++) {
        float4 e = eb4[i];
        float zq0, zq1, zq2, zq3;
        asm("mov.b64 {%0, %1}, %2;" : "=f"(zq0), "=f"(zq1) : "l"(zr[2 * i]));
        asm("mov.b64 {%0, %1}, %2;" : "=f"(zq2), "=f"(zq3) : "l"(zr[2 * i + 1]));
        float q0 = __fadd_rn(zq0, __fsub_rn(e.x, zq0));
        float q1 = __fadd_rn(zq1, __fsub_rn(e.y, zq1));
        float q2 = __fadd_rn(zq2, __fsub_rn(e.z, zq2));
        float q3 = __fadd_rn(zq3, __fsub_rn(e.w, zq3));
        float d0 = __fsub_rn(q0, zq0);
        float d1 = __fsub_rn(q1, zq1);
        float d2 = __fsub_rn(q2, zq2);
        float d3 = __fsub_rn(q3, zq3);
        lsum += d0 * d0 + d1 * d1 + d2 * d2 + d3 * d3;
        oz[(size_t)(4 * i + 0) * SP] = q0;
        oz[(size_t)(4 * i + 1) * SP] = q1;
        oz[(size_t)(4 * i + 2) * SP] = q2;
        oz[(size_t)(4 * i + 3) * SP] = q3;
    }

    if (write_idx) out[(size_t)NZQ + 1 + row] = (float)bk;

    // Deterministic block reduction of the loss partial
    const int lane = tid & 31;
    const int wrp = tid >> 5;
#pragma unroll
    for (int off = 16; off; off >>= 1)
        lsum += __shfl_down_sync(0xffffffffu, lsum, off);
    if (lane == 0) wsum[wrp] = lsum;
    __syncthreads();
    if (tid == 0) {
        double sd = 0.0;
#pragma unroll
        for (int w = 0; w < BLK / 32; w++) sd += (double)wsum[w];
        g_partial[blockIdx.x] = sd;
        __threadfence();
        unsigned old = atomicAdd(&g_ctr, 1u);
        is_last = (old == NBLOCKS - 1) ? 1 : 0;
    }
    __syncthreads();

    // Last finishing block performs the final deterministic reduction.
    if (is_last) {
        double sacc = 0.0;
#pragma unroll
        for (int i = 0; i < NBLOCKS / BLK; i++) {
            double v;
            asm volatile("ld.global.cg.f64 %0, [%1];"
                         : "=d"(v) : "l"(&g_partial[tid + i * BLK]));
            sacc += v;
        }
        dsum[tid] = sacc;
        __syncthreads();
        for (int st = BLK / 2; st >= 1; st >>= 1) {
            if (tid < st) dsum[tid] += dsum[tid + st];
            __syncthreads();
        }
        if (tid == 0) {
            if (write_loss)
                out[NZQ] = (float)(1.25 * dsum[0] / (double)NZQ);
            g_ctr = 0;   // reset for next graph replay
        }
    }
}

// ---------------------------------------------------------------------------
extern "C" void kernel_launch(void* const* d_in, const int* in_sizes, int n_in,
                              void* d_out, int out_size) {
    const float* z = (const float*)d_in[0];
    const float* emb = (const float*)d_in[1];
    // Defensive: identify tensors by element count (z: 4194304, emb: 65536)
    if (n_in >= 2 && in_sizes[0] == KCODES * NC && in_sizes[1] == NZQ) {
        const float* tmp = z; z = emb; emb = tmp;
    }
    float* out = (float*)d_out;
    const int write_loss = (out_size >= NZQ + 1) ? 1 : 0;
    const int write_idx = (out_size >= NZQ + 1 + NROWS) ? 1 : 0;

    vq_fused_kernel<<<NROWS / BLK, BLK>>>(z, emb, out, write_idx, write_loss);
}

// round 5
// speedup vs baseline: 1.2173x; 1.2173x over previous
#include <cuda_runtime.h>

// Problem constants (z: (4,64,16,32,32) f32, emb: (1024,64) f32)
#define NBATCH 4
#define NC     64
#define SP     16384            // 16*32*32 spatial per batch
#define NROWS  (NBATCH * SP)    // 65536
#define KCODES 1024
#define TK     64               // codebook tile per smem pass
#define NTILES (KCODES / TK)    // 16
#define NZQ    (NBATCH * NC * SP)  // 4194304
#define BLK    128
#define RPT    2                // rows per thread
#define ROWS_PER_BLK (BLK * RPT)
#define NBLOCKS (NROWS / ROWS_PER_BLK)   // 256

__device__ double g_partial[NBLOCKS];
__device__ unsigned g_ctr = 0;

// ---------------------------------------------------------------------------
// cp.async helpers
// ---------------------------------------------------------------------------
__device__ __forceinline__ void cp_async16(unsigned smem_addr, const void* gptr) {
    asm volatile("cp.async.cg.shared.global [%0], [%1], 16;\n"
                 :: "r"(smem_addr), "l"(gptr));
}
__device__ __forceinline__ void cp_commit() {
    asm volatile("cp.async.commit_group;\n");
}
template <int N>
__device__ __forceinline__ void cp_wait() {
    asm volatile("cp.async.wait_group %0;\n" :: "n"(N));
}

#define FMA2(acc, x, y) \
    asm("fma.rn.f32x2 %0, %1, %2, %0;" : "+l"(acc) : "l"(x), "l"(y))
#define ADD2(a, b) \
    asm("add.rn.f32x2 %0, %0, %1;" : "+l"(a) : "l"(b))

// ---------------------------------------------------------------------------
// Fused kernel: per-block e2 prep, 2-row-per-thread VQ argmin sweep,
// STE epilogue, last-block deterministic loss finalization.
// ---------------------------------------------------------------------------
__global__ void __launch_bounds__(BLK, 2)
vq_fused_kernel(const float* __restrict__ z, const float* __restrict__ emb,
                float* __restrict__ out, int write_idx, int write_loss) {
    __shared__ __align__(16) float se[2][TK * NC];   // 2 x 16 KB codebook tiles
    __shared__ __align__(16) float e2s[KCODES];      // 4 KB: all code norms
    __shared__ float wsum[BLK / 32];
    __shared__ double dsum[BLK];
    __shared__ int is_last;

    const int tid = threadIdx.x;
    const int row0 = blockIdx.x * ROWS_PER_BLK + tid;
    const int row1 = row0 + BLK;

    // Issue tile 0 and tile 1 codebook loads up front (depth-2 cp.async).
#pragma unroll
    for (int t = 0; t < 2; t++) {
        unsigned sb = (unsigned)__cvta_generic_to_shared(&se[t][0]);
        const char* gb = (const char*)(emb + (size_t)t * TK * NC);
#pragma unroll
        for (int j = 0; j < (TK * NC * 4) / (BLK * 16); j++)
            cp_async16(sb + (tid + j * BLK) * 16, gb + (tid + j * BLK) * 16);
        cp_commit();
    }

    // Per-block e2 (identical expression to round-1 prep → identical rounding)
    for (int k = tid; k < KCODES; k += BLK) {
        const float4* e = (const float4*)(emb + (size_t)k * NC);
        float sacc = 0.f;
#pragma unroll
        for (int i = 0; i < NC / 4; i++) {
            float4 v = e[i];
            sacc += v.x * v.x + v.y * v.y + v.z * v.z + v.w * v.w;
        }
        e2s[k] = sacc;
    }

    // Load both rows' z values (coalesced: stride SP per channel) and build
    // per-row z2 (balanced pairwise tree, IDENTICAL to round 1) + packed z.
    unsigned long long zr0[NC / 2], zr1[NC / 2];
    float z2_0, z2_1;
#pragma unroll
    for (int r = 0; r < RPT; r++) {
        const int row = r ? row1 : row0;
        const int b = row >> 14;
        const int s = row & (SP - 1);
        const float* zp = z + (size_t)b * NC * SP + s;
        float zv[NC];
#pragma unroll
        for (int c = 0; c < NC; c++) zv[c] = zp[(size_t)c * SP];
        float t32[32];
#pragma unroll
        for (int i = 0; i < 32; i++)
            t32[i] = __fadd_rn(__fmul_rn(zv[2 * i], zv[2 * i]),
                               __fmul_rn(zv[2 * i + 1], zv[2 * i + 1]));
#pragma unroll
        for (int st = 16; st >= 1; st >>= 1)
#pragma unroll
            for (int i = 0; i < 16; i++)
                if (i < st) t32[i] = __fadd_rn(t32[i], t32[i + st]);
        if (r == 0) z2_0 = t32[0]; else z2_1 = t32[0];
        unsigned long long* zr = r ? zr1 : zr0;
#pragma unroll
        for (int j = 0; j < NC / 2; j++)
            asm("mov.b64 %0, {%1, %2};" : "=l"(zr[j]) : "f"(zv[2 * j]), "f"(zv[2 * j + 1]));
    }

    __syncthreads();   // e2s ready

    float best0 = __int_as_float(0x7f800000), best1 = best0;
    int bk0 = 0, bk1 = 0;

    for (int t = 0; t < NTILES; t++) {
        if (t < NTILES - 1) cp_wait<1>(); else cp_wait<0>();
        __syncthreads();

        const int buf = t & 1;
        const int k0 = t * TK;

#pragma unroll 2
        for (int kk = 0; kk < TK; kk++) {
            const ulonglong2* ep = (const ulonglong2*)(&se[buf][kk * NC]);
            unsigned long long a0 = 0ull, a1 = 0ull, a2 = 0ull, a3 = 0ull;
            unsigned long long c0 = 0ull, c1 = 0ull, c2 = 0ull, c3 = 0ull;
#pragma unroll
            for (int i = 0; i < 8; i++) {
                ulonglong2 e01 = ep[2 * i];
                ulonglong2 e23 = ep[2 * i + 1];
                FMA2(a0, zr0[4 * i + 0], e01.x);
                FMA2(a1, zr0[4 * i + 1], e01.y);
                FMA2(a2, zr0[4 * i + 2], e23.x);
                FMA2(a3, zr0[4 * i + 3], e23.y);
                FMA2(c0, zr1[4 * i + 0], e01.x);
                FMA2(c1, zr1[4 * i + 1], e01.y);
                FMA2(c2, zr1[4 * i + 2], e23.x);
                FMA2(c3, zr1[4 * i + 3], e23.y);
            }
            const float e2k = e2s[k0 + kk];
            // Row 0 tail (identical op order to round 1)
            ADD2(a0, a1); ADD2(a2, a3); ADD2(a0, a2);
            float lo, hi;
            asm("mov.b64 {%0, %1}, %2;" : "=f"(lo), "=f"(hi) : "l"(a0));
            const float dot0 = __fadd_rn(lo, hi);
            const float sc0 = __fsub_rn(__fadd_rn(z2_0, e2k), 2.0f * dot0);
            if (sc0 < best0) { best0 = sc0; bk0 = k0 + kk; }
            // Row 1 tail
            ADD2(c0, c1); ADD2(c2, c3); ADD2(c0, c2);
            asm("mov.b64 {%0, %1}, %2;" : "=f"(lo), "=f"(hi) : "l"(c0));
            const float dot1 = __fadd_rn(lo, hi);
            const float sc1 = __fsub_rn(__fadd_rn(z2_1, e2k), 2.0f * dot1);
            if (sc1 < best1) { best1 = sc1; bk1 = k0 + kk; }
        }

        __syncthreads();
        if (t + 2 < NTILES) {
            unsigned sb = (unsigned)__cvta_generic_to_shared(&se[buf][0]);
            const char* gb = (const char*)(emb + (size_t)(t + 2) * TK * NC);
#pragma unroll
            for (int j = 0; j < (TK * NC * 4) / (BLK * 16); j++)
                cp_async16(sb + (tid + j * BLK) * 16, gb + (tid + j * BLK) * 16);
            cp_commit();
        }
    }

    // Epilogue (IDENTICAL per-row numerics to round 1)
    float lsum = 0.f;
#pragma unroll
    for (int r = 0; r < RPT; r++) {
        const int row = r ? row1 : row0;
        const int bk = r ? bk1 : bk0;
        const unsigned long long* zr = r ? zr1 : zr0;
        const int b = row >> 14;
        const int s = row & (SP - 1);
        const float4* eb4 = (const float4*)(emb + (size_t)bk * NC);
        float* oz = out + (size_t)b * NC * SP + s;
#pragma unroll
        for (int i = 0; i < NC / 4; i++) {
            float4 e = eb4[i];
            float zq0, zq1, zq2, zq3;
            asm("mov.b64 {%0, %1}, %2;" : "=f"(zq0), "=f"(zq1) : "l"(zr[2 * i]));
            asm("mov.b64 {%0, %1}, %2;" : "=f"(zq2), "=f"(zq3) : "l"(zr[2 * i + 1]));
            float q0 = __fadd_rn(zq0, __fsub_rn(e.x, zq0));
            float q1 = __fadd_rn(zq1, __fsub_rn(e.y, zq1));
            float q2 = __fadd_rn(zq2, __fsub_rn(e.z, zq2));
            float q3 = __fadd_rn(zq3, __fsub_rn(e.w, zq3));
            float d0 = __fsub_rn(q0, zq0);
            float d1 = __fsub_rn(q1, zq1);
            float d2 = __fsub_rn(q2, zq2);
            float d3 = __fsub_rn(q3, zq3);
            lsum += d0 * d0 + d1 * d1 + d2 * d2 + d3 * d3;
            oz[(size_t)(4 * i + 0) * SP] = q0;
            oz[(size_t)(4 * i + 1) * SP] = q1;
            oz[(size_t)(4 * i + 2) * SP] = q2;
            oz[(size_t)(4 * i + 3) * SP] = q3;
        }
        if (write_idx) out[(size_t)NZQ + 1 + row] = (float)bk;
    }

    // Deterministic block reduction of the loss partial
    const int lane = tid & 31;
    const int wrp = tid >> 5;
#pragma unroll
    for (int off = 16; off; off >>= 1)
        lsum += __shfl_down_sync(0xffffffffu, lsum, off);
    if (lane == 0) wsum[wrp] = lsum;
    __syncthreads();
    if (tid == 0) {
        double sd = 0.0;
#pragma unroll
        for (int w = 0; w < BLK / 32; w++) sd += (double)wsum[w];
        g_partial[blockIdx.x] = sd;
        __threadfence();
        unsigned old = atomicAdd(&g_ctr, 1u);
        is_last = (old == NBLOCKS - 1) ? 1 : 0;
    }
    __syncthreads();

    // Last finishing block: final deterministic reduction.
    if (is_last) {
        double sacc = 0.0;
#pragma unroll
        for (int i = 0; i < NBLOCKS / BLK; i++) {
            double v;
            asm volatile("ld.global.cg.f64 %0, [%1];"
                         : "=d"(v) : "l"(&g_partial[tid + i * BLK]));
            sacc += v;
        }
        dsum[tid] = sacc;
        __syncthreads();
        for (int st = BLK / 2; st >= 1; st >>= 1) {
            if (tid < st) dsum[tid] += dsum[tid + st];
            __syncthreads();
        }
        if (tid == 0) {
            if (write_loss)
                out[NZQ] = (float)(1.25 * dsum[0] / (double)NZQ);
            g_ctr = 0;   // reset for next graph replay
        }
    }
}

// ---------------------------------------------------------------------------
extern "C" void kernel_launch(void* const* d_in, const int* in_sizes, int n_in,
                              void* d_out, int out_size) {
    const float* z = (const float*)d_in[0];
    const float* emb = (const float*)d_in[1];
    // Defensive: identify tensors by element count (z: 4194304, emb: 65536)
    if (n_in >= 2 && in_sizes[0] == KCODES * NC && in_sizes[1] == NZQ) {
        const float* tmp = z; z = emb; emb = tmp;
    }
    float* out = (float*)d_out;
    const int write_loss = (out_size >= NZQ + 1) ? 1 : 0;
    const int write_idx = (out_size >= NZQ + 1 + NROWS) ? 1 : 0;

    vq_fused_kernel<<<NBLOCKS, BLK>>>(z, emb, out, write_idx, write_loss);
}

// round 6
// speedup vs baseline: 1.3336x; 1.0956x over previous
#include <cuda_runtime.h>

// Problem constants (z: (4,64,16,32,32) f32, emb: (1024,64) f32)
#define NBATCH 4
#define NC     64
#define SP     16384            // 16*32*32 spatial per batch
#define NROWS  (NBATCH * SP)    // 65536
#define KCODES 1024
#define KHALF  (KCODES / 2)     // 512 codes per k-slice
#define TK     64               // codebook tile per smem pass
#define NTILESH (KHALF / TK)    // 8 tiles per half
#define NZQ    (NBATCH * NC * SP)  // 4194304
#define BLK    128
#define RPT    2                // rows per thread
#define ROWS_PER_CHUNK (BLK * RPT)          // 256
#define NCHUNKS (NROWS / ROWS_PER_CHUNK)    // 256
#define NBLK_EPI 512

__device__ float  g_e2[KCODES];
__device__ float  g_sc[2][NROWS];    // per-half best score
__device__ int    g_bk[2][NROWS];    // per-half best index
__device__ double g_partial[NBLK_EPI];

// ---------------------------------------------------------------------------
// cp.async helpers
// ---------------------------------------------------------------------------
__device__ __forceinline__ void cp_async16(unsigned smem_addr, const void* gptr) {
    asm volatile("cp.async.cg.shared.global [%0], [%1], 16;\n"
                 :: "r"(smem_addr), "l"(gptr));
}
__device__ __forceinline__ void cp_commit() {
    asm volatile("cp.async.commit_group;\n");
}
template <int N>
__device__ __forceinline__ void cp_wait() {
    asm volatile("cp.async.wait_group %0;\n" :: "n"(N));
}

#define FMA2(acc, x, y) \
    asm("fma.rn.f32x2 %0, %1, %2, %0;" : "+l"(acc) : "l"(x), "l"(y))
#define ADD2(a, b) \
    asm("add.rn.f32x2 %0, %0, %1;" : "+l"(a) : "l"(b))

// ---------------------------------------------------------------------------
// Kernel 1: per-code squared norms (IDENTICAL contraction to round 1)
// ---------------------------------------------------------------------------
__global__ void prep_kernel(const float* __restrict__ emb) {
    int k = blockIdx.x * blockDim.x + threadIdx.x;
    if (k < KCODES) {
        const float4* e = (const float4*)(emb + k * NC);
        float s = 0.f;
#pragma unroll
        for (int i = 0; i < NC / 4; i++) {
            float4 v = e[i];
            s += v.x * v.x + v.y * v.y + v.z * v.z + v.w * v.w;
        }
        g_e2[k] = s;
    }
}

// ---------------------------------------------------------------------------
// Kernel 2: sweep — block = (row-chunk, k-half). 2 rows/thread, frozen
// score numerics, writes (best score, best index) for its half.
// ---------------------------------------------------------------------------
__global__ void __launch_bounds__(BLK, 3)
sweep_kernel(const float* __restrict__ z, const float* __restrict__ emb) {
    __shared__ __align__(16) float se[2][TK * NC];   // 2 x 16 KB codebook tiles
    __shared__ __align__(16) float e2h[KHALF];       // 2 KB: this half's norms

    const int tid = threadIdx.x;
    const int chunk = blockIdx.x >> 1;
    const int kh = blockIdx.x & 1;
    const int kbase = kh * KHALF;
    const float* embh = emb + (size_t)kbase * NC;

    const int row0 = chunk * ROWS_PER_CHUNK + tid;
    const int row1 = row0 + BLK;

    // Prime tiles 0,1 of this half + the half's e2 (cp.async)
#pragma unroll
    for (int t = 0; t < 2; t++) {
        unsigned sb = (unsigned)__cvta_generic_to_shared(&se[t][0]);
        const char* gb = (const char*)(embh + (size_t)t * TK * NC);
#pragma unroll
        for (int j = 0; j < (TK * NC * 4) / (BLK * 16); j++)
            cp_async16(sb + (tid + j * BLK) * 16, gb + (tid + j * BLK) * 16);
        if (t == 0)
            cp_async16((unsigned)__cvta_generic_to_shared(&e2h[tid * 4]),
                       &g_e2[kbase + tid * 4]);
        cp_commit();
    }

    // Load both rows' z (coalesced) + frozen pairwise z2 + pack to f32x2
    unsigned long long zr0[NC / 2], zr1[NC / 2];
    float z2_0, z2_1;
#pragma unroll
    for (int r = 0; r < RPT; r++) {
        const int row = r ? row1 : row0;
        const int b = row >> 14;
        const int s = row & (SP - 1);
        const float* zp = z + (size_t)b * NC * SP + s;
        float zv[NC];
#pragma unroll
        for (int c = 0; c < NC; c++) zv[c] = zp[(size_t)c * SP];
        float t32[32];
#pragma unroll
        for (int i = 0; i < 32; i++)
            t32[i] = __fadd_rn(__fmul_rn(zv[2 * i], zv[2 * i]),
                               __fmul_rn(zv[2 * i + 1], zv[2 * i + 1]));
#pragma unroll
        for (int st = 16; st >= 1; st >>= 1)
#pragma unroll
            for (int i = 0; i < 16; i++)
                if (i < st) t32[i] = __fadd_rn(t32[i], t32[i + st]);
        if (r == 0) z2_0 = t32[0]; else z2_1 = t32[0];
        unsigned long long* zr = r ? zr1 : zr0;
#pragma unroll
        for (int j = 0; j < NC / 2; j++)
            asm("mov.b64 %0, {%1, %2};" : "=l"(zr[j]) : "f"(zv[2 * j]), "f"(zv[2 * j + 1]));
    }

    float best0 = __int_as_float(0x7f800000), best1 = best0;
    int bk0 = kbase, bk1 = kbase;

    for (int t = 0; t < NTILESH; t++) {
        if (t < NTILESH - 1) cp_wait<1>(); else cp_wait<0>();
        __syncthreads();

        const int buf = t & 1;
        const int k0 = kbase + t * TK;

        for (int kk = 0; kk < TK; kk++) {
            const ulonglong2* ep = (const ulonglong2*)(&se[buf][kk * NC]);
            unsigned long long a0 = 0ull, a1 = 0ull, a2 = 0ull, a3 = 0ull;
            unsigned long long c0 = 0ull, c1 = 0ull, c2 = 0ull, c3 = 0ull;
#pragma unroll
            for (int i = 0; i < 8; i++) {
                ulonglong2 e01 = ep[2 * i];
                ulonglong2 e23 = ep[2 * i + 1];
                FMA2(a0, zr0[4 * i + 0], e01.x);
                FMA2(a1, zr0[4 * i + 1], e01.y);
                FMA2(a2, zr0[4 * i + 2], e23.x);
                FMA2(a3, zr0[4 * i + 3], e23.y);
                FMA2(c0, zr1[4 * i + 0], e01.x);
                FMA2(c1, zr1[4 * i + 1], e01.y);
                FMA2(c2, zr1[4 * i + 2], e23.x);
                FMA2(c3, zr1[4 * i + 3], e23.y);
            }
            const float e2k = e2h[t * TK + kk];
            // Row 0 tail (frozen op order)
            ADD2(a0, a1); ADD2(a2, a3); ADD2(a0, a2);
            float lo, hi;
            asm("mov.b64 {%0, %1}, %2;" : "=f"(lo), "=f"(hi) : "l"(a0));
            const float dot0 = __fadd_rn(lo, hi);
            const float sc0 = __fsub_rn(__fadd_rn(z2_0, e2k), 2.0f * dot0);
            if (sc0 < best0) { best0 = sc0; bk0 = k0 + kk; }
            // Row 1 tail
            ADD2(c0, c1); ADD2(c2, c3); ADD2(c0, c2);
            asm("mov.b64 {%0, %1}, %2;" : "=f"(lo), "=f"(hi) : "l"(c0));
            const float dot1 = __fadd_rn(lo, hi);
            const float sc1 = __fsub_rn(__fadd_rn(z2_1, e2k), 2.0f * dot1);
            if (sc1 < best1) { best1 = sc1; bk1 = k0 + kk; }
        }

        __syncthreads();
        if (t + 2 < NTILESH) {
            unsigned sb = (unsigned)__cvta_generic_to_shared(&se[buf][0]);
            const char* gb = (const char*)(embh + (size_t)(t + 2) * TK * NC);
#pragma unroll
            for (int j = 0; j < (TK * NC * 4) / (BLK * 16); j++)
                cp_async16(sb + (tid + j * BLK) * 16, gb + (tid + j * BLK) * 16);
            cp_commit();
        }
    }

    g_sc[kh][row0] = best0;
    g_bk[kh][row0] = bk0;
    g_sc[kh][row1] = best1;
    g_bk[kh][row1] = bk1;
}

// ---------------------------------------------------------------------------
// Kernel 3: merge halves + STE epilogue + loss partials (1 row/thread).
// Merge: strict < picks the upper half; ties keep lower half (lower index)
// → identical to a single ascending-k first-min scan.
// ---------------------------------------------------------------------------
__global__ void __launch_bounds__(BLK)
epi_kernel(const float* __restrict__ z, const float* __restrict__ emb,
           float* __restrict__ out, int write_idx) {
    __shared__ float wsum[BLK / 32];
    const int tid = threadIdx.x;
    const int row = blockIdx.x * BLK + tid;
    const int b = row >> 14;
    const int s = row & (SP - 1);

    const float scA = g_sc[0][row];
    const float scB = g_sc[1][row];
    const int bk = (scB < scA) ? g_bk[1][row] : g_bk[0][row];

    const float* zp = z + (size_t)b * NC * SP + s;
    const float4* eb4 = (const float4*)(emb + (size_t)bk * NC);
    float* oz = out + (size_t)b * NC * SP + s;

    float lsum = 0.f;
#pragma unroll
    for (int i = 0; i < NC / 4; i++) {
        float4 e = eb4[i];
        float zq0 = zp[(size_t)(4 * i + 0) * SP];
        float zq1 = zp[(size_t)(4 * i + 1) * SP];
        float zq2 = zp[(size_t)(4 * i + 2) * SP];
        float zq3 = zp[(size_t)(4 * i + 3) * SP];
        // Frozen STE numerics: q = zc + (e - zc)
        float q0 = __fadd_rn(zq0, __fsub_rn(e.x, zq0));
        float q1 = __fadd_rn(zq1, __fsub_rn(e.y, zq1));
        float q2 = __fadd_rn(zq2, __fsub_rn(e.z, zq2));
        float q3 = __fadd_rn(zq3, __fsub_rn(e.w, zq3));
        float d0 = __fsub_rn(q0, zq0);
        float d1 = __fsub_rn(q1, zq1);
        float d2 = __fsub_rn(q2, zq2);
        float d3 = __fsub_rn(q3, zq3);
        lsum += d0 * d0 + d1 * d1 + d2 * d2 + d3 * d3;
        oz[(size_t)(4 * i + 0) * SP] = q0;
        oz[(size_t)(4 * i + 1) * SP] = q1;
        oz[(size_t)(4 * i + 2) * SP] = q2;
        oz[(size_t)(4 * i + 3) * SP] = q3;
    }

    if (write_idx) out[(size_t)NZQ + 1 + row] = (float)bk;

    // Deterministic block reduction of the loss partial
    const int lane = tid & 31;
    const int wrp = tid >> 5;
#pragma unroll
    for (int off = 16; off; off >>= 1)
        lsum += __shfl_down_sync(0xffffffffu, lsum, off);
    if (lane == 0) wsum[wrp] = lsum;
    __syncthreads();
    if (tid == 0) {
        double sd = 0.0;
#pragma unroll
        for (int w = 0; w < BLK / 32; w++) sd += (double)wsum[w];
        g_partial[blockIdx.x] = sd;
    }
}

// ---------------------------------------------------------------------------
// Kernel 4: deterministic final loss reduction
// ---------------------------------------------------------------------------
__global__ void fin_kernel(float* __restrict__ out, int write_loss) {
    __shared__ double sd[256];
    int t = threadIdx.x;
    double s = 0.0;
#pragma unroll
    for (int i = 0; i < NBLK_EPI / 256; i++) s += g_partial[t + i * 256];
    sd[t] = s;
    __syncthreads();
    for (int st = 128; st >= 1; st >>= 1) {
        if (t < st) sd[t] += sd[t + st];
        __syncthreads();
    }
    if (t == 0 && write_loss) {
        // vq_loss = 1.25 * mean(d^2)
        out[NZQ] = (float)(1.25 * sd[0] / (double)NZQ);
    }
}

// ---------------------------------------------------------------------------
extern "C" void kernel_launch(void* const* d_in, const int* in_sizes, int n_in,
                              void* d_out, int out_size) {
    const float* z = (const float*)d_in[0];
    const float* emb = (const float*)d_in[1];
    // Defensive: identify tensors by element count (z: 4194304, emb: 65536)
    if (n_in >= 2 && in_sizes[0] == KCODES * NC && in_sizes[1] == NZQ) {
        const float* tmp = z; z = emb; emb = tmp;
    }
    float* out = (float*)d_out;
    const int write_loss = (out_size >= NZQ + 1) ? 1 : 0;
    const int write_idx = (out_size >= NZQ + 1 + NROWS) ? 1 : 0;

    prep_kernel<<<(KCODES + 127) / 128, 128>>>(emb);
    sweep_kernel<<<NCHUNKS * 2, BLK>>>(z, emb);
    epi_kernel<<<NBLK_EPI, BLK>>>(z, emb, out, write_idx);
    fin_kernel<<<1, 256>>>(out, write_loss);
}

// round 7
// speedup vs baseline: 1.4571x; 1.0926x over previous
#include <cuda_runtime.h>

// Problem constants (z: (4,64,16,32,32) f32, emb: (1024,64) f32)
#define NBATCH 4
#define NC     64
#define SP     16384            // 16*32*32 spatial per batch
#define NROWS  (NBATCH * SP)    // 65536
#define KCODES 1024
#define TK     64               // codebook tile (smem buffer granularity)
#define NZQ    (NBATCH * NC * SP)  // 4194304
#define BLK    128
#define RPT    2                // rows per thread
#define ROWS_PER_CHUNK (BLK * RPT)          // 256
#define NCHUNKS (NROWS / ROWS_PER_CHUNK)    // 256
#define NSLICE 8
#define CPS    (KCODES / NSLICE)            // 128 codes per slice
#define NITEMS (NCHUNKS * NSLICE)           // 2048
#define GRID_SWEEP 444                      // 148 SMs * 3 target blocks
#define NBLK_EPI (NROWS / BLK)              // 512

__device__ float  g_e2[KCODES];
__device__ float  g_sc[NSLICE][NROWS];   // per-slice best score
__device__ int    g_bk[NSLICE][NROWS];   // per-slice best index
__device__ double g_partial[NBLK_EPI];
__device__ unsigned g_item = 0;

// ---------------------------------------------------------------------------
// cp.async helpers
// ---------------------------------------------------------------------------
__device__ __forceinline__ void cp_async16(unsigned smem_addr, const void* gptr) {
    asm volatile("cp.async.cg.shared.global [%0], [%1], 16;\n"
                 :: "r"(smem_addr), "l"(gptr));
}
__device__ __forceinline__ void cp_commit() {
    asm volatile("cp.async.commit_group;\n");
}
template <int N>
__device__ __forceinline__ void cp_wait() {
    asm volatile("cp.async.wait_group %0;\n" :: "n"(N));
}

#define FMA2(acc, x, y) \
    asm("fma.rn.f32x2 %0, %1, %2, %0;" : "+l"(acc) : "l"(x), "l"(y))
#define ADD2(a, b) \
    asm("add.rn.f32x2 %0, %0, %1;" : "+l"(a) : "l"(b))

// ---------------------------------------------------------------------------
// Kernel 1: per-code squared norms (IDENTICAL contraction to round 1)
// ---------------------------------------------------------------------------
__global__ void prep_kernel(const float* __restrict__ emb) {
    int k = blockIdx.x * blockDim.x + threadIdx.x;
    if (k < KCODES) {
        const float4* e = (const float4*)(emb + k * NC);
        float s = 0.f;
#pragma unroll
        for (int i = 0; i < NC / 4; i++) {
            float4 v = e[i];
            s += v.x * v.x + v.y * v.y + v.z * v.z + v.w * v.w;
        }
        g_e2[k] = s;
    }
}

// ---------------------------------------------------------------------------
// Kernel 2: persistent sweep — dynamic queue of (chunk, k-slice) items.
// 2 rows/thread, frozen score numerics, per-slice (score, index) results.
// ---------------------------------------------------------------------------
__global__ void __launch_bounds__(BLK, 3)
sweep_kernel(const float* __restrict__ z, const float* __restrict__ emb) {
    __shared__ __align__(16) float se[2][TK * NC];   // 2 x 16 KB codebook tiles
    __shared__ __align__(16) float e2h[CPS];         // this slice's norms
    __shared__ unsigned s_item;

    const int tid = threadIdx.x;

    for (;;) {
        __syncthreads();   // barrier A: smem safe for reuse, s_item consumed
        if (tid == 0) s_item = atomicAdd(&g_item, 1u);
        __syncthreads();   // barrier B: s_item visible
        const unsigned it = s_item;
        if (it >= NITEMS) break;

        const int chunk = it >> 3;
        const int slice = it & (NSLICE - 1);
        const int kbase = slice * CPS;
        const float* embs = emb + (size_t)kbase * NC;

        // Issue both tiles of this slice (group0 = tile0 + e2, group1 = tile1)
#pragma unroll
        for (int t = 0; t < 2; t++) {
            unsigned sb = (unsigned)__cvta_generic_to_shared(&se[t][0]);
            const char* gb = (const char*)(embs + (size_t)t * TK * NC);
#pragma unroll
            for (int j = 0; j < (TK * NC * 4) / (BLK * 16); j++)
                cp_async16(sb + (tid + j * BLK) * 16, gb + (tid + j * BLK) * 16);
            if (t == 0 && tid < CPS / 4)
                cp_async16((unsigned)__cvta_generic_to_shared(&e2h[tid * 4]),
                           &g_e2[kbase + tid * 4]);
            cp_commit();
        }

        const int row0 = chunk * ROWS_PER_CHUNK + tid;
        const int row1 = row0 + BLK;

        // Load both rows' z (coalesced) + frozen pairwise z2 + pack to f32x2
        unsigned long long zr0[NC / 2], zr1[NC / 2];
        float z2_0, z2_1;
#pragma unroll
        for (int r = 0; r < RPT; r++) {
            const int row = r ? row1 : row0;
            const int b = row >> 14;
            const int s = row & (SP - 1);
            const float* zp = z + (size_t)b * NC * SP + s;
            float zv[NC];
#pragma unroll
            for (int c = 0; c < NC; c++) zv[c] = zp[(size_t)c * SP];
            float t32[32];
#pragma unroll
            for (int i = 0; i < 32; i++)
                t32[i] = __fadd_rn(__fmul_rn(zv[2 * i], zv[2 * i]),
                                   __fmul_rn(zv[2 * i + 1], zv[2 * i + 1]));
#pragma unroll
            for (int st = 16; st >= 1; st >>= 1)
#pragma unroll
                for (int i = 0; i < 16; i++)
                    if (i < st) t32[i] = __fadd_rn(t32[i], t32[i + st]);
            if (r == 0) z2_0 = t32[0]; else z2_1 = t32[0];
            unsigned long long* zr = r ? zr1 : zr0;
#pragma unroll
            for (int j = 0; j < NC / 2; j++)
                asm("mov.b64 %0, {%1, %2};" : "=l"(zr[j]) : "f"(zv[2 * j]), "f"(zv[2 * j + 1]));
        }

        float best0 = __int_as_float(0x7f800000), best1 = best0;
        int bk0 = kbase, bk1 = kbase;

#pragma unroll
        for (int t = 0; t < 2; t++) {
            if (t == 0) cp_wait<1>(); else cp_wait<0>();
            __syncthreads();
            const int k0 = kbase + t * TK;

            for (int kk = 0; kk < TK; kk++) {
                const ulonglong2* ep = (const ulonglong2*)(&se[t][kk * NC]);
                unsigned long long a0 = 0ull, a1 = 0ull, a2 = 0ull, a3 = 0ull;
                unsigned long long c0 = 0ull, c1 = 0ull, c2 = 0ull, c3 = 0ull;
#pragma unroll
                for (int i = 0; i < 8; i++) {
                    ulonglong2 e01 = ep[2 * i];
                    ulonglong2 e23 = ep[2 * i + 1];
                    FMA2(a0, zr0[4 * i + 0], e01.x);
                    FMA2(a1, zr0[4 * i + 1], e01.y);
                    FMA2(a2, zr0[4 * i + 2], e23.x);
                    FMA2(a3, zr0[4 * i + 3], e23.y);
                    FMA2(c0, zr1[4 * i + 0], e01.x);
                    FMA2(c1, zr1[4 * i + 1], e01.y);
                    FMA2(c2, zr1[4 * i + 2], e23.x);
                    FMA2(c3, zr1[4 * i + 3], e23.y);
                }
                const float e2k = e2h[t * TK + kk];
                // Row 0 tail (frozen op order)
                ADD2(a0, a1); ADD2(a2, a3); ADD2(a0, a2);
                float lo, hi;
                asm("mov.b64 {%0, %1}, %2;" : "=f"(lo), "=f"(hi) : "l"(a0));
                const float dot0 = __fadd_rn(lo, hi);
                const float sc0 = __fsub_rn(__fadd_rn(z2_0, e2k), 2.0f * dot0);
                if (sc0 < best0) { best0 = sc0; bk0 = k0 + kk; }
                // Row 1 tail
                ADD2(c0, c1); ADD2(c2, c3); ADD2(c0, c2);
                asm("mov.b64 {%0, %1}, %2;" : "=f"(lo), "=f"(hi) : "l"(c0));
                const float dot1 = __fadd_rn(lo, hi);
                const float sc1 = __fsub_rn(__fadd_rn(z2_1, e2k), 2.0f * dot1);
                if (sc1 < best1) { best1 = sc1; bk1 = k0 + kk; }
            }
        }

        g_sc[slice][row0] = best0;
        g_bk[slice][row0] = bk0;
        g_sc[slice][row1] = best1;
        g_bk[slice][row1] = bk1;
    }
}

// ---------------------------------------------------------------------------
// Kernel 3: merge slices + STE epilogue + loss partials (1 row/thread).
// Ascending-slice scan with strict < == global ascending-k first-min.
// ---------------------------------------------------------------------------
__global__ void __launch_bounds__(BLK)
epi_kernel(const float* __restrict__ z, const float* __restrict__ emb,
           float* __restrict__ out, int write_idx) {
    __shared__ float wsum[BLK / 32];
    const int tid = threadIdx.x;
    const int row = blockIdx.x * BLK + tid;
    const int b = row >> 14;
    const int s = row & (SP - 1);

    float best = g_sc[0][row];
    int bk = g_bk[0][row];
#pragma unroll
    for (int sl = 1; sl < NSLICE; sl++) {
        const float scs = g_sc[sl][row];
        if (scs < best) { best = scs; bk = g_bk[sl][row]; }
    }

    const float* zp = z + (size_t)b * NC * SP + s;
    const float4* eb4 = (const float4*)(emb + (size_t)bk * NC);
    float* oz = out + (size_t)b * NC * SP + s;

    float lsum = 0.f;
#pragma unroll
    for (int i = 0; i < NC / 4; i++) {
        float4 e = eb4[i];
        float zq0 = zp[(size_t)(4 * i + 0) * SP];
        float zq1 = zp[(size_t)(4 * i + 1) * SP];
        float zq2 = zp[(size_t)(4 * i + 2) * SP];
        float zq3 = zp[(size_t)(4 * i + 3) * SP];
        // Frozen STE numerics: q = zc + (e - zc)
        float q0 = __fadd_rn(zq0, __fsub_rn(e.x, zq0));
        float q1 = __fadd_rn(zq1, __fsub_rn(e.y, zq1));
        float q2 = __fadd_rn(zq2, __fsub_rn(e.z, zq2));
        float q3 = __fadd_rn(zq3, __fsub_rn(e.w, zq3));
        float d0 = __fsub_rn(q0, zq0);
        float d1 = __fsub_rn(q1, zq1);
        float d2 = __fsub_rn(q2, zq2);
        float d3 = __fsub_rn(q3, zq3);
        lsum += d0 * d0 + d1 * d1 + d2 * d2 + d3 * d3;
        oz[(size_t)(4 * i + 0) * SP] = q0;
        oz[(size_t)(4 * i + 1) * SP] = q1;
        oz[(size_t)(4 * i + 2) * SP] = q2;
        oz[(size_t)(4 * i + 3) * SP] = q3;
    }

    if (write_idx) out[(size_t)NZQ + 1 + row] = (float)bk;

    // Deterministic block reduction of the loss partial
    const int lane = tid & 31;
    const int wrp = tid >> 5;
#pragma unroll
    for (int off = 16; off; off >>= 1)
        lsum += __shfl_down_sync(0xffffffffu, lsum, off);
    if (lane == 0) wsum[wrp] = lsum;
    __syncthreads();
    if (tid == 0) {
        double sd = 0.0;
#pragma unroll
        for (int w = 0; w < BLK / 32; w++) sd += (double)wsum[w];
        g_partial[blockIdx.x] = sd;
    }
}

// ---------------------------------------------------------------------------
// Kernel 4: deterministic final loss reduction + work-queue reset
// ---------------------------------------------------------------------------
__global__ void fin_kernel(float* __restrict__ out, int write_loss) {
    __shared__ double sd[256];
    int t = threadIdx.x;
    double s = 0.0;
#pragma unroll
    for (int i = 0; i < NBLK_EPI / 256; i++) s += g_partial[t + i * 256];
    sd[t] = s;
    __syncthreads();
    for (int st = 128; st >= 1; st >>= 1) {
        if (t < st) sd[t] += sd[t + st];
        __syncthreads();
    }
    if (t == 0) {
        if (write_loss)
            out[NZQ] = (float)(1.25 * sd[0] / (double)NZQ);
        g_item = 0;   // reset the work queue for the next graph replay
    }
}

// ---------------------------------------------------------------------------
extern "C" void kernel_launch(void* const* d_in, const int* in_sizes, int n_in,
                              void* d_out, int out_size) {
    const float* z = (const float*)d_in[0];
    const float* emb = (const float*)d_in[1];
    // Defensive: identify tensors by element count (z: 4194304, emb: 65536)
    if (n_in >= 2 && in_sizes[0] == KCODES * NC && in_sizes[1] == NZQ) {
        const float* tmp = z; z = emb; emb = tmp;
    }
    float* out = (float*)d_out;
    const int write_loss = (out_size >= NZQ + 1) ? 1 : 0;
    const int write_idx = (out_size >= NZQ + 1 + NROWS) ? 1 : 0;

    prep_kernel<<<(KCODES + 127) / 128, 128>>>(emb);
    sweep_kernel<<<GRID_SWEEP, BLK>>>(z, emb);
    epi_kernel<<<NBLK_EPI, BLK>>>(z, emb, out, write_idx);
    fin_kernel<<<1, 256>>>(out, write_loss);
}